// round 4
// baseline (speedup 1.0000x reference)
#include <cuda_runtime.h>
#include <math.h>

#define BATCH   2
#define S_LEN   2048
#define HEADS   16
#define HD      64
#define DM      1024
#define M_TOT   (BATCH * S_LEN)          // 4096

// ---------------- scratch (device globals: allocation-free) ----------------
__device__ float g_q[BATCH * HEADS * S_LEN * HD];    // [B,H,S,64]
__device__ float g_k[BATCH * HEADS * S_LEN * HD];
__device__ float g_v[BATCH * HEADS * S_LEN * HD];
__device__ float g_cat[BATCH * S_LEN * DM];          // [B,S,H*64]

// ---------------- SGEMM: C = A[M,K] * W[N,K]^T + bias ----------------------
// 128x128 tile, BK=8, 256 threads, 8x8 per-thread micro-tile.
// scatter==1: write into [B,H,S,64] layout (n -> h,d ; m -> b,s)
// scatter==0: write row-major C[m*N + n]
#define GBM 128
#define GBN 128
#define GBK 8

__global__ __launch_bounds__(256) void sgemm_kernel(
    const float* __restrict__ A, const float* __restrict__ W,
    const float* __restrict__ bias, float* __restrict__ C,
    int M, int N, int K, int scatter)
{
    __shared__ float As[GBK][GBM];
    __shared__ float Bs[GBK][GBN];

    const int tid = threadIdx.x;
    const int bm = blockIdx.y * GBM;
    const int bn = blockIdx.x * GBN;
    const int tr = tid >> 4;          // 0..15
    const int tc = tid & 15;          // 0..15

    float acc[8][8];
#pragma unroll
    for (int i = 0; i < 8; i++)
#pragma unroll
        for (int j = 0; j < 8; j++) acc[i][j] = 0.f;

    const int lrow = tid >> 1;            // 0..127
    const int lcol = (tid & 1) << 2;      // 0 or 4
    const float* Aptr = A + (size_t)(bm + lrow) * K + lcol;
    const float* Wptr = W + (size_t)(bn + lrow) * K + lcol;

    for (int kt = 0; kt < K; kt += GBK) {
        float4 av = *(const float4*)(Aptr + kt);
        float4 wv = *(const float4*)(Wptr + kt);
        As[lcol + 0][lrow] = av.x;
        As[lcol + 1][lrow] = av.y;
        As[lcol + 2][lrow] = av.z;
        As[lcol + 3][lrow] = av.w;
        Bs[lcol + 0][lrow] = wv.x;
        Bs[lcol + 1][lrow] = wv.y;
        Bs[lcol + 2][lrow] = wv.z;
        Bs[lcol + 3][lrow] = wv.w;
        __syncthreads();

#pragma unroll
        for (int k = 0; k < GBK; k++) {
            float rm[8], rn[8];
            *(float4*)(rm)     = *(const float4*)&As[k][tr * 8];
            *(float4*)(rm + 4) = *(const float4*)&As[k][tr * 8 + 4];
            *(float4*)(rn)     = *(const float4*)&Bs[k][tc * 8];
            *(float4*)(rn + 4) = *(const float4*)&Bs[k][tc * 8 + 4];
#pragma unroll
            for (int i = 0; i < 8; i++)
#pragma unroll
                for (int j = 0; j < 8; j++)
                    acc[i][j] = fmaf(rm[i], rn[j], acc[i][j]);
        }
        __syncthreads();
    }

    if (scatter) {
#pragma unroll
        for (int i = 0; i < 8; i++) {
            int m = bm + tr * 8 + i;
            int b = m >> 11;             // /2048
            int s = m & 2047;
#pragma unroll
            for (int j = 0; j < 8; j++) {
                int n = bn + tc * 8 + j;
                int h = n >> 6;
                int d = n & 63;
                C[(((size_t)b * HEADS + h) * S_LEN + s) * HD + d] = acc[i][j] + bias[n];
            }
        }
    } else {
#pragma unroll
        for (int i = 0; i < 8; i++) {
            int m = bm + tr * 8 + i;
#pragma unroll
            for (int j = 0; j < 8; j++) {
                int n = bn + tc * 8 + j;
                C[(size_t)m * N + n] = acc[i][j] + bias[n];
            }
        }
    }
}

// ---------------- Flash attention (fp32) -----------------------------------
// grid: (S/64, H, B); 256 threads as 16x16, each owns 4x4 fragment.
// smem: Qs[64][68] (scaled), Kt[64][68] (kdim-major), Vs[64][68], Ps[64][68], cmask[64]
#define PADW 68
#define TILE_F (64 * PADW)

__global__ __launch_bounds__(256) void attn_kernel(
    const float* __restrict__ Qb, const float* __restrict__ Kb,
    const float* __restrict__ Vb, const int* __restrict__ mask,
    float* __restrict__ Oc)
{
    extern __shared__ float sm[];
    float* Qs = sm;
    float* Kt = sm + TILE_F;
    float* Vs = sm + 2 * TILE_F;
    float* Ps = sm + 3 * TILE_F;
    int*   cm = (int*)(sm + 4 * TILE_F);

    const int it = blockIdx.x;
    const int h  = blockIdx.y;
    const int b  = blockIdx.z;
    const int tid = threadIdx.x;
    const int ty = tid >> 4;
    const int tx = tid & 15;

    const size_t bh = ((size_t)b * HEADS + h) * S_LEN * HD;
    const float scale = 0.125f;   // 1/sqrt(64)

    // load + scale Q tile
    for (int e = tid; e < 1024; e += 256) {
        int r = e >> 4;
        int c = (e & 15) << 2;
        float4 v = *(const float4*)(Qb + bh + (size_t)(it * 64 + r) * HD + c);
        Qs[r * PADW + c + 0] = v.x * scale;
        Qs[r * PADW + c + 1] = v.y * scale;
        Qs[r * PADW + c + 2] = v.z * scale;
        Qs[r * PADW + c + 3] = v.w * scale;
    }

    float m_i[4], l_i[4], o[4][4];
#pragma unroll
    for (int r = 0; r < 4; r++) {
        m_i[r] = -1e30f;
        l_i[r] = 0.f;
#pragma unroll
        for (int c = 0; c < 4; c++) o[r][c] = 0.f;
    }
    __syncthreads();

    for (int jt = 0; jt <= it; jt++) {
        // load K (k-major transpose) and V tiles
        for (int e = tid; e < 1024; e += 256) {
            int r = e >> 4;
            int c = (e & 15) << 2;
            float4 kv = *(const float4*)(Kb + bh + (size_t)(jt * 64 + r) * HD + c);
            Kt[(c + 0) * PADW + r] = kv.x;
            Kt[(c + 1) * PADW + r] = kv.y;
            Kt[(c + 2) * PADW + r] = kv.z;
            Kt[(c + 3) * PADW + r] = kv.w;
            float4 vv = *(const float4*)(Vb + bh + (size_t)(jt * 64 + r) * HD + c);
            *(float4*)&Vs[r * PADW + c] = vv;
        }
        if (tid < 64) cm[tid] = mask[b * S_LEN + jt * 64 + tid];
        __syncthreads();

        // scores S = Qs * Kt  (4x4 per thread)
        float s[4][4];
#pragma unroll
        for (int r = 0; r < 4; r++)
#pragma unroll
            for (int c = 0; c < 4; c++) s[r][c] = 0.f;

#pragma unroll 8
        for (int kd = 0; kd < 64; kd++) {
            float4 kr = *(const float4*)&Kt[kd * PADW + tx * 4];
            float kk[4] = {kr.x, kr.y, kr.z, kr.w};
#pragma unroll
            for (int r = 0; r < 4; r++) {
                float q = Qs[(ty * 4 + r) * PADW + kd];
#pragma unroll
                for (int c = 0; c < 4; c++)
                    s[r][c] = fmaf(q, kk[c], s[r][c]);
            }
        }

        const bool diag = (jt == it);
#pragma unroll
        for (int r = 0; r < 4; r++) {
            int gr = it * 64 + ty * 4 + r;
            bool valid[4];
            float mx = -1e30f;
#pragma unroll
            for (int c = 0; c < 4; c++) {
                int lc = tx * 4 + c;
                int gc = jt * 64 + lc;
                valid[c] = ((!diag) || (gc <= gr)) && (cm[lc] != 0);
                if (valid[c]) mx = fmaxf(mx, s[r][c]);
            }
#pragma unroll
            for (int off = 1; off < 16; off <<= 1)
                mx = fmaxf(mx, __shfl_xor_sync(0xffffffffu, mx, off));

            float mnew = fmaxf(m_i[r], mx);
            float alpha = __expf(m_i[r] - mnew);   // 0 when m_i=-1e30, 1 when both -1e30
            float ls = 0.f;
            float p[4];
#pragma unroll
            for (int c = 0; c < 4; c++) {
                p[c] = valid[c] ? __expf(s[r][c] - mnew) : 0.f;
                ls += p[c];
            }
#pragma unroll
            for (int off = 1; off < 16; off <<= 1)
                ls += __shfl_xor_sync(0xffffffffu, ls, off);

            l_i[r] = l_i[r] * alpha + ls;
            m_i[r] = mnew;
#pragma unroll
            for (int c = 0; c < 4; c++) {
                o[r][c] *= alpha;
                Ps[(ty * 4 + r) * PADW + tx * 4 + c] = p[c];
            }
        }
        __syncthreads();

        // O += P * V
#pragma unroll 8
        for (int n = 0; n < 64; n++) {
            float4 vr = *(const float4*)&Vs[n * PADW + tx * 4];
            float vv[4] = {vr.x, vr.y, vr.z, vr.w};
#pragma unroll
            for (int r = 0; r < 4; r++) {
                float pp = Ps[(ty * 4 + r) * PADW + n];
#pragma unroll
                for (int c = 0; c < 4; c++)
                    o[r][c] = fmaf(pp, vv[c], o[r][c]);
            }
        }
        __syncthreads();
    }

    // epilogue: normalize and write concat [B,S,H*64]
#pragma unroll
    for (int r = 0; r < 4; r++) {
        int s_idx = it * 64 + ty * 4 + r;
        int rv = mask[b * S_LEN + s_idx];
        float inv = (l_i[r] > 0.f && rv != 0) ? (1.f / l_i[r]) : 0.f;
#pragma unroll
        for (int c = 0; c < 4; c++)
            Oc[((size_t)b * S_LEN + s_idx) * DM + h * HD + tx * 4 + c] = o[r][c] * inv;
    }
}

// ---------------- host ------------------------------------------------------
extern "C" void kernel_launch(void* const* d_in, const int* in_sizes, int n_in,
                              void* d_out, int out_size)
{
    const float* x    = (const float*)d_in[0];
    const int*   mask = (const int*)  d_in[1];
    const float* Wq   = (const float*)d_in[2];
    const float* bq   = (const float*)d_in[3];
    const float* Wk   = (const float*)d_in[4];
    const float* bk   = (const float*)d_in[5];
    const float* Wv   = (const float*)d_in[6];
    const float* bv   = (const float*)d_in[7];
    const float* Wo   = (const float*)d_in[8];
    const float* bo   = (const float*)d_in[9];
    float* out = (float*)d_out;

    float *qp, *kp, *vp, *cp;
    cudaGetSymbolAddress((void**)&qp, g_q);
    cudaGetSymbolAddress((void**)&kp, g_k);
    cudaGetSymbolAddress((void**)&vp, g_v);
    cudaGetSymbolAddress((void**)&cp, g_cat);

    dim3 gproj(DM / GBN, M_TOT / GBM);   // (8, 32)
    sgemm_kernel<<<gproj, 256>>>(x, Wq, bq, qp, M_TOT, DM, DM, 1);
    sgemm_kernel<<<gproj, 256>>>(x, Wk, bk, kp, M_TOT, DM, DM, 1);
    sgemm_kernel<<<gproj, 256>>>(x, Wv, bv, vp, M_TOT, DM, DM, 1);

    static int smem_set = 0;
    size_t smem = (size_t)(4 * TILE_F) * sizeof(float) + 64 * sizeof(int);
    if (!smem_set) {
        cudaFuncSetAttribute(attn_kernel, cudaFuncAttributeMaxDynamicSharedMemorySize, (int)smem);
        smem_set = 1;
    }
    dim3 gattn(S_LEN / 64, HEADS, BATCH);  // (32, 16, 2)
    attn_kernel<<<gattn, 256, smem>>>(qp, kp, vp, mask, cp);

    sgemm_kernel<<<gproj, 256>>>(cp, Wo, bo, out, M_TOT, DM, DM, 0);
}

// round 7
// speedup vs baseline: 1.5747x; 1.5747x over previous
#include <cuda_runtime.h>
#include <math.h>

#define BATCH   2
#define S_LEN   2048
#define HEADS   16
#define HD      64
#define DM      1024
#define M_TOT   (BATCH * S_LEN)          // 4096

// ---------------- scratch (device globals: allocation-free) ----------------
__device__ float g_q[BATCH * HEADS * S_LEN * HD];    // [B,H,S,64]
__device__ float g_k[BATCH * HEADS * S_LEN * HD];
__device__ float g_v[BATCH * HEADS * S_LEN * HD];
__device__ float g_cat[BATCH * S_LEN * DM];          // [B,S,H*64]

// ---------------- tf32 tensor-core GEMM ------------------------------------
// C[M,N] = A[M,K] * W[N,K]^T + bias, M=4096, N=1024, K=1024 (all four GEMMs).
// 128x128 CTA tile, BK=32, 8 warps (2x4), warp tile 64x32 via m16n8k8 tf32.
// scatter==1: write into [B,H,S,64] layout; scatter==0: row-major.

#define LDA 36   // padded smem stride (floats): bank = (4*group + tig) % 32, conflict-free

__device__ __forceinline__ unsigned f2tf(float x) {
    unsigned r;
    asm("cvt.rna.tf32.f32 %0, %1;" : "=r"(r) : "f"(x));
    return r;
}

__device__ __forceinline__ void mma_tf32(float* c, const unsigned* a, const unsigned* b) {
    asm volatile(
        "mma.sync.aligned.m16n8k8.row.col.f32.tf32.tf32.f32 "
        "{%0,%1,%2,%3}, {%4,%5,%6,%7}, {%8,%9}, {%0,%1,%2,%3};\n"
        : "+f"(c[0]), "+f"(c[1]), "+f"(c[2]), "+f"(c[3])
        : "r"(a[0]), "r"(a[1]), "r"(a[2]), "r"(a[3]), "r"(b[0]), "r"(b[1]));
}

__global__ __launch_bounds__(256) void gemm_tf32(
    const float* __restrict__ A, const float* __restrict__ W,
    const float* __restrict__ bias, float* __restrict__ C, int scatter)
{
    __shared__ unsigned As[128 * LDA];
    __shared__ unsigned Ws[128 * LDA];

    const int tid  = threadIdx.x;
    const int lane = tid & 31;
    const int wid  = tid >> 5;
    const int wm   = wid >> 2;        // 0..1  -> m offset wm*64
    const int wn   = wid & 3;         // 0..3  -> n offset wn*32
    const int bm   = blockIdx.y * 128;
    const int bn   = blockIdx.x * 128;

    const int grp = lane >> 2;        // 0..7
    const int tig = lane & 3;         // 0..3

    const int lrow = tid >> 1;        // 0..127
    const int lcol = (tid & 1) * 16;  // 0 or 16

    const float* Ap = A + (size_t)(bm + lrow) * DM + lcol;
    const float* Wp = W + (size_t)(bn + lrow) * DM + lcol;

    float c[4][4][4];
#pragma unroll
    for (int i = 0; i < 4; i++)
#pragma unroll
        for (int j = 0; j < 4; j++)
#pragma unroll
            for (int r = 0; r < 4; r++) c[i][j][r] = 0.f;

    // prefetch first k-slab
    float4 pa[4], pw[4];
#pragma unroll
    for (int u = 0; u < 4; u++) {
        pa[u] = *(const float4*)(Ap + u * 4);
        pw[u] = *(const float4*)(Wp + u * 4);
    }

    for (int kt = 0; kt < DM; kt += 32) {
        unsigned* as = &As[lrow * LDA + lcol];
        unsigned* ws = &Ws[lrow * LDA + lcol];
#pragma unroll
        for (int u = 0; u < 4; u++) {
            as[u * 4 + 0] = f2tf(pa[u].x);
            as[u * 4 + 1] = f2tf(pa[u].y);
            as[u * 4 + 2] = f2tf(pa[u].z);
            as[u * 4 + 3] = f2tf(pa[u].w);
            ws[u * 4 + 0] = f2tf(pw[u].x);
            ws[u * 4 + 1] = f2tf(pw[u].y);
            ws[u * 4 + 2] = f2tf(pw[u].z);
            ws[u * 4 + 3] = f2tf(pw[u].w);
        }
        __syncthreads();

        if (kt + 32 < DM) {
#pragma unroll
            for (int u = 0; u < 4; u++) {
                pa[u] = *(const float4*)(Ap + kt + 32 + u * 4);
                pw[u] = *(const float4*)(Wp + kt + 32 + u * 4);
            }
        }

#pragma unroll
        for (int ks = 0; ks < 4; ks++) {
            unsigned b[4][2];
#pragma unroll
            for (int j = 0; j < 4; j++) {
                int n = wn * 32 + j * 8 + grp;
                int k = ks * 8 + tig;
                b[j][0] = Ws[n * LDA + k];
                b[j][1] = Ws[n * LDA + k + 4];
            }
#pragma unroll
            for (int i = 0; i < 4; i++) {
                unsigned a[4];
                int m = wm * 64 + i * 16 + grp;
                int k = ks * 8 + tig;
                a[0] = As[m * LDA + k];
                a[1] = As[(m + 8) * LDA + k];
                a[2] = As[m * LDA + k + 4];
                a[3] = As[(m + 8) * LDA + k + 4];
#pragma unroll
                for (int j = 0; j < 4; j++)
                    mma_tf32(c[i][j], a, b[j]);
            }
        }
        __syncthreads();
    }

    // epilogue: bias + store (float2 per c-pair)
#pragma unroll
    for (int j = 0; j < 4; j++) {
        int n0 = bn + wn * 32 + j * 8 + 2 * tig;
        float bia0 = bias[n0];
        float bia1 = bias[n0 + 1];
#pragma unroll
        for (int i = 0; i < 4; i++) {
            int m0 = bm + wm * 64 + i * 16 + grp;
            float2 v0 = make_float2(c[i][j][0] + bia0, c[i][j][1] + bia1);
            float2 v1 = make_float2(c[i][j][2] + bia0, c[i][j][3] + bia1);
            if (scatter) {
                int h = n0 >> 6, d = n0 & 63;
                int b0 = m0 >> 11, s0 = m0 & 2047;
                int b1 = (m0 + 8) >> 11, s1 = (m0 + 8) & 2047;
                *(float2*)&C[(((size_t)b0 * HEADS + h) * S_LEN + s0) * HD + d] = v0;
                *(float2*)&C[(((size_t)b1 * HEADS + h) * S_LEN + s1) * HD + d] = v1;
            } else {
                *(float2*)&C[(size_t)m0 * DM + n0] = v0;
                *(float2*)&C[(size_t)(m0 + 8) * DM + n0] = v1;
            }
        }
    }
}

// ---------------- Flash attention (fp32) -----------------------------------
// grid: (S/64, H, B); 256 threads as 16x16, each owns 4x4 fragment.
#define PADW 68
#define TILE_F (64 * PADW)

__global__ __launch_bounds__(256) void attn_kernel(
    const float* __restrict__ Qb, const float* __restrict__ Kb,
    const float* __restrict__ Vb, const int* __restrict__ mask,
    float* __restrict__ Oc)
{
    extern __shared__ float sm[];
    float* Qs = sm;
    float* Kt = sm + TILE_F;
    float* Vs = sm + 2 * TILE_F;
    float* Ps = sm + 3 * TILE_F;
    int*   cm = (int*)(sm + 4 * TILE_F);

    const int it = blockIdx.x;
    const int h  = blockIdx.y;
    const int b  = blockIdx.z;
    const int tid = threadIdx.x;
    const int ty = tid >> 4;
    const int tx = tid & 15;

    const size_t bh = ((size_t)b * HEADS + h) * S_LEN * HD;
    const float scale = 0.125f;   // 1/sqrt(64)

    for (int e = tid; e < 1024; e += 256) {
        int r = e >> 4;
        int c = (e & 15) << 2;
        float4 v = *(const float4*)(Qb + bh + (size_t)(it * 64 + r) * HD + c);
        Qs[r * PADW + c + 0] = v.x * scale;
        Qs[r * PADW + c + 1] = v.y * scale;
        Qs[r * PADW + c + 2] = v.z * scale;
        Qs[r * PADW + c + 3] = v.w * scale;
    }

    float m_i[4], l_i[4], o[4][4];
#pragma unroll
    for (int r = 0; r < 4; r++) {
        m_i[r] = -1e30f;
        l_i[r] = 0.f;
#pragma unroll
        for (int c = 0; c < 4; c++) o[r][c] = 0.f;
    }
    __syncthreads();

    for (int jt = 0; jt <= it; jt++) {
        for (int e = tid; e < 1024; e += 256) {
            int r = e >> 4;
            int c = (e & 15) << 2;
            float4 kv = *(const float4*)(Kb + bh + (size_t)(jt * 64 + r) * HD + c);
            Kt[(c + 0) * PADW + r] = kv.x;
            Kt[(c + 1) * PADW + r] = kv.y;
            Kt[(c + 2) * PADW + r] = kv.z;
            Kt[(c + 3) * PADW + r] = kv.w;
            float4 vv = *(const float4*)(Vb + bh + (size_t)(jt * 64 + r) * HD + c);
            *(float4*)&Vs[r * PADW + c] = vv;
        }
        if (tid < 64) cm[tid] = mask[b * S_LEN + jt * 64 + tid];
        __syncthreads();

        float s[4][4];
#pragma unroll
        for (int r = 0; r < 4; r++)
#pragma unroll
            for (int c = 0; c < 4; c++) s[r][c] = 0.f;

#pragma unroll 8
        for (int kd = 0; kd < 64; kd++) {
            float4 kr = *(const float4*)&Kt[kd * PADW + tx * 4];
            float kk[4] = {kr.x, kr.y, kr.z, kr.w};
#pragma unroll
            for (int r = 0; r < 4; r++) {
                float q = Qs[(ty * 4 + r) * PADW + kd];
#pragma unroll
                for (int c = 0; c < 4; c++)
                    s[r][c] = fmaf(q, kk[c], s[r][c]);
            }
        }

        const bool diag = (jt == it);
#pragma unroll
        for (int r = 0; r < 4; r++) {
            int gr = it * 64 + ty * 4 + r;
            bool valid[4];
            float mx = -1e30f;
#pragma unroll
            for (int c = 0; c < 4; c++) {
                int lc = tx * 4 + c;
                int gc = jt * 64 + lc;
                valid[c] = ((!diag) || (gc <= gr)) && (cm[lc] != 0);
                if (valid[c]) mx = fmaxf(mx, s[r][c]);
            }
#pragma unroll
            for (int off = 1; off < 16; off <<= 1)
                mx = fmaxf(mx, __shfl_xor_sync(0xffffffffu, mx, off));

            float mnew = fmaxf(m_i[r], mx);
            float alpha = __expf(m_i[r] - mnew);
            float ls = 0.f;
            float p[4];
#pragma unroll
            for (int c = 0; c < 4; c++) {
                p[c] = valid[c] ? __expf(s[r][c] - mnew) : 0.f;
                ls += p[c];
            }
#pragma unroll
            for (int off = 1; off < 16; off <<= 1)
                ls += __shfl_xor_sync(0xffffffffu, ls, off);

            l_i[r] = l_i[r] * alpha + ls;
            m_i[r] = mnew;
#pragma unroll
            for (int c = 0; c < 4; c++) {
                o[r][c] *= alpha;
                Ps[(ty * 4 + r) * PADW + tx * 4 + c] = p[c];
            }
        }
        __syncthreads();

#pragma unroll 8
        for (int n = 0; n < 64; n++) {
            float4 vr = *(const float4*)&Vs[n * PADW + tx * 4];
            float vv[4] = {vr.x, vr.y, vr.z, vr.w};
#pragma unroll
            for (int r = 0; r < 4; r++) {
                float pp = Ps[(ty * 4 + r) * PADW + n];
#pragma unroll
                for (int c = 0; c < 4; c++)
                    o[r][c] = fmaf(pp, vv[c], o[r][c]);
            }
        }
        __syncthreads();
    }

#pragma unroll
    for (int r = 0; r < 4; r++) {
        int s_idx = it * 64 + ty * 4 + r;
        int rv = mask[b * S_LEN + s_idx];
        float inv = (l_i[r] > 0.f && rv != 0) ? (1.f / l_i[r]) : 0.f;
#pragma unroll
        for (int c = 0; c < 4; c++)
            Oc[((size_t)b * S_LEN + s_idx) * DM + h * HD + tx * 4 + c] = o[r][c] * inv;
    }
}

// ---------------- host ------------------------------------------------------
extern "C" void kernel_launch(void* const* d_in, const int* in_sizes, int n_in,
                              void* d_out, int out_size)
{
    const float* x    = (const float*)d_in[0];
    const int*   mask = (const int*)  d_in[1];
    const float* Wq   = (const float*)d_in[2];
    const float* bq   = (const float*)d_in[3];
    const float* Wk   = (const float*)d_in[4];
    const float* bk   = (const float*)d_in[5];
    const float* Wv   = (const float*)d_in[6];
    const float* bv   = (const float*)d_in[7];
    const float* Wo   = (const float*)d_in[8];
    const float* bo   = (const float*)d_in[9];
    float* out = (float*)d_out;

    float *qp, *kp, *vp, *cp;
    cudaGetSymbolAddress((void**)&qp, g_q);
    cudaGetSymbolAddress((void**)&kp, g_k);
    cudaGetSymbolAddress((void**)&vp, g_v);
    cudaGetSymbolAddress((void**)&cp, g_cat);

    dim3 ggemm(DM / 128, M_TOT / 128);   // (8, 32)
    gemm_tf32<<<ggemm, 256>>>(x, Wq, bq, qp, 1);
    gemm_tf32<<<ggemm, 256>>>(x, Wk, bk, kp, 1);
    gemm_tf32<<<ggemm, 256>>>(x, Wv, bv, vp, 1);

    static int smem_set = 0;
    size_t smem = (size_t)(4 * TILE_F) * sizeof(float) + 64 * sizeof(int);
    if (!smem_set) {
        cudaFuncSetAttribute(attn_kernel, cudaFuncAttributeMaxDynamicSharedMemorySize, (int)smem);
        smem_set = 1;
    }
    dim3 gattn(S_LEN / 64, HEADS, BATCH);  // (32, 16, 2)
    attn_kernel<<<gattn, 256, smem>>>(qp, kp, vp, mask, cp);

    gemm_tf32<<<ggemm, 256>>>(cp, Wo, bo, out, 0);
}

// round 9
// speedup vs baseline: 1.6053x; 1.0194x over previous
#include <cuda_runtime.h>
#include <math.h>

#define BATCH   2
#define S_LEN   2048
#define HEADS   16
#define HD      64
#define DM      1024
#define M_TOT   (BATCH * S_LEN)          // 4096

// ---------------- scratch (device globals: allocation-free) ----------------
__device__ float g_q[BATCH * HEADS * S_LEN * HD];    // [B,H,S,64]
__device__ float g_k[BATCH * HEADS * S_LEN * HD];
__device__ float g_v[BATCH * HEADS * S_LEN * HD];
__device__ float g_cat[BATCH * S_LEN * DM];          // [B,S,H*64]

// ---------------- tf32 tensor-core GEMM ------------------------------------
// C[M,N] = A[M,K] * W[N,K]^T + bias, M=4096, N=1024, K=1024 (all four GEMMs).
// 128x128 CTA tile, BK=32, 8 warps (2x4), warp tile 64x32 via m16n8k8 tf32.
// scatter==1: write into [B,H,S,64] layout; scatter==0: row-major.

#define LDA 36   // padded smem stride (floats): bank = (4*group + tig) % 32, conflict-free

__device__ __forceinline__ unsigned f2tf(float x) {
    unsigned r;
    asm("cvt.rna.tf32.f32 %0, %1;" : "=r"(r) : "f"(x));
    return r;
}

__device__ __forceinline__ void mma_tf32(float* c, const unsigned* a, const unsigned* b) {
    asm volatile(
        "mma.sync.aligned.m16n8k8.row.col.f32.tf32.tf32.f32 "
        "{%0,%1,%2,%3}, {%4,%5,%6,%7}, {%8,%9}, {%0,%1,%2,%3};\n"
        : "+f"(c[0]), "+f"(c[1]), "+f"(c[2]), "+f"(c[3])
        : "r"(a[0]), "r"(a[1]), "r"(a[2]), "r"(a[3]), "r"(b[0]), "r"(b[1]));
}

__global__ __launch_bounds__(256) void gemm_tf32(
    const float* __restrict__ A, const float* __restrict__ W,
    const float* __restrict__ bias, float* __restrict__ C, int scatter)
{
    __shared__ unsigned As[128 * LDA];
    __shared__ unsigned Ws[128 * LDA];

    const int tid  = threadIdx.x;
    const int lane = tid & 31;
    const int wid  = tid >> 5;
    const int wm   = wid >> 2;        // 0..1  -> m offset wm*64
    const int wn   = wid & 3;         // 0..3  -> n offset wn*32
    const int bm   = blockIdx.y * 128;
    const int bn   = blockIdx.x * 128;

    const int grp = lane >> 2;        // 0..7
    const int tig = lane & 3;         // 0..3

    const int lrow = tid >> 1;        // 0..127
    const int lcol = (tid & 1) * 16;  // 0 or 16

    const float* Ap = A + (size_t)(bm + lrow) * DM + lcol;
    const float* Wp = W + (size_t)(bn + lrow) * DM + lcol;

    float c[4][4][4];
#pragma unroll
    for (int i = 0; i < 4; i++)
#pragma unroll
        for (int j = 0; j < 4; j++)
#pragma unroll
            for (int r = 0; r < 4; r++) c[i][j][r] = 0.f;

    // prefetch first k-slab
    float4 pa[4], pw[4];
#pragma unroll
    for (int u = 0; u < 4; u++) {
        pa[u] = *(const float4*)(Ap + u * 4);
        pw[u] = *(const float4*)(Wp + u * 4);
    }

    for (int kt = 0; kt < DM; kt += 32) {
        unsigned* as = &As[lrow * LDA + lcol];
        unsigned* ws = &Ws[lrow * LDA + lcol];
#pragma unroll
        for (int u = 0; u < 4; u++) {
            as[u * 4 + 0] = f2tf(pa[u].x);
            as[u * 4 + 1] = f2tf(pa[u].y);
            as[u * 4 + 2] = f2tf(pa[u].z);
            as[u * 4 + 3] = f2tf(pa[u].w);
            ws[u * 4 + 0] = f2tf(pw[u].x);
            ws[u * 4 + 1] = f2tf(pw[u].y);
            ws[u * 4 + 2] = f2tf(pw[u].z);
            ws[u * 4 + 3] = f2tf(pw[u].w);
        }
        __syncthreads();

        if (kt + 32 < DM) {
#pragma unroll
            for (int u = 0; u < 4; u++) {
                pa[u] = *(const float4*)(Ap + kt + 32 + u * 4);
                pw[u] = *(const float4*)(Wp + kt + 32 + u * 4);
            }
        }

#pragma unroll
        for (int ks = 0; ks < 4; ks++) {
            unsigned b[4][2];
#pragma unroll
            for (int j = 0; j < 4; j++) {
                int n = wn * 32 + j * 8 + grp;
                int k = ks * 8 + tig;
                b[j][0] = Ws[n * LDA + k];
                b[j][1] = Ws[n * LDA + k + 4];
            }
#pragma unroll
            for (int i = 0; i < 4; i++) {
                unsigned a[4];
                int m = wm * 64 + i * 16 + grp;
                int k = ks * 8 + tig;
                a[0] = As[m * LDA + k];
                a[1] = As[(m + 8) * LDA + k];
                a[2] = As[m * LDA + k + 4];
                a[3] = As[(m + 8) * LDA + k + 4];
#pragma unroll
                for (int j = 0; j < 4; j++)
                    mma_tf32(c[i][j], a, b[j]);
            }
        }
        __syncthreads();
    }

    // epilogue: bias + store (float2 per c-pair)
#pragma unroll
    for (int j = 0; j < 4; j++) {
        int n0 = bn + wn * 32 + j * 8 + 2 * tig;
        float bia0 = bias[n0];
        float bia1 = bias[n0 + 1];
#pragma unroll
        for (int i = 0; i < 4; i++) {
            int m0 = bm + wm * 64 + i * 16 + grp;
            float2 v0 = make_float2(c[i][j][0] + bia0, c[i][j][1] + bia1);
            float2 v1 = make_float2(c[i][j][2] + bia0, c[i][j][3] + bia1);
            if (scatter) {
                int h = n0 >> 6, d = n0 & 63;
                int b0 = m0 >> 11, s0 = m0 & 2047;
                int b1 = (m0 + 8) >> 11, s1 = (m0 + 8) & 2047;
                *(float2*)&C[(((size_t)b0 * HEADS + h) * S_LEN + s0) * HD + d] = v0;
                *(float2*)&C[(((size_t)b1 * HEADS + h) * S_LEN + s1) * HD + d] = v1;
            } else {
                *(float2*)&C[(size_t)m0 * DM + n0] = v0;
                *(float2*)&C[(size_t)(m0 + 8) * DM + n0] = v1;
            }
        }
    }
}

// ---------------- Flash attention (fp32) -----------------------------------
// grid: (S/64, H, B); 256 threads as 16x16, each owns 4x4 fragment.
#define PADW 68
#define TILE_F (64 * PADW)

__global__ __launch_bounds__(256) void attn_kernel(
    const float* __restrict__ Qb, const float* __restrict__ Kb,
    const float* __restrict__ Vb, const int* __restrict__ mask,
    float* __restrict__ Oc)
{
    extern __shared__ float sm[];
    float* Qs = sm;
    float* Kt = sm + TILE_F;
    float* Vs = sm + 2 * TILE_F;
    float* Ps = sm + 3 * TILE_F;
    int*   cm = (int*)(sm + 4 * TILE_F);

    const int it = blockIdx.x;
    const int h  = blockIdx.y;
    const int b  = blockIdx.z;
    const int tid = threadIdx.x;
    const int ty = tid >> 4;
    const int tx = tid & 15;

    const size_t bh = ((size_t)b * HEADS + h) * S_LEN * HD;
    const float scale = 0.125f;   // 1/sqrt(64)

    for (int e = tid; e < 1024; e += 256) {
        int r = e >> 4;
        int c = (e & 15) << 2;
        float4 v = *(const float4*)(Qb + bh + (size_t)(it * 64 + r) * HD + c);
        Qs[r * PADW + c + 0] = v.x * scale;
        Qs[r * PADW + c + 1] = v.y * scale;
        Qs[r * PADW + c + 2] = v.z * scale;
        Qs[r * PADW + c + 3] = v.w * scale;
    }

    float m_i[4], l_i[4], o[4][4];
#pragma unroll
    for (int r = 0; r < 4; r++) {
        m_i[r] = -1e30f;
        l_i[r] = 0.f;
#pragma unroll
        for (int c = 0; c < 4; c++) o[r][c] = 0.f;
    }
    __syncthreads();

    for (int jt = 0; jt <= it; jt++) {
        for (int e = tid; e < 1024; e += 256) {
            int r = e >> 4;
            int c = (e & 15) << 2;
            float4 kv = *(const float4*)(Kb + bh + (size_t)(jt * 64 + r) * HD + c);
            Kt[(c + 0) * PADW + r] = kv.x;
            Kt[(c + 1) * PADW + r] = kv.y;
            Kt[(c + 2) * PADW + r] = kv.z;
            Kt[(c + 3) * PADW + r] = kv.w;
            float4 vv = *(const float4*)(Vb + bh + (size_t)(jt * 64 + r) * HD + c);
            *(float4*)&Vs[r * PADW + c] = vv;
        }
        if (tid < 64) cm[tid] = mask[b * S_LEN + jt * 64 + tid];
        __syncthreads();

        float s[4][4];
#pragma unroll
        for (int r = 0; r < 4; r++)
#pragma unroll
            for (int c = 0; c < 4; c++) s[r][c] = 0.f;

#pragma unroll 8
        for (int kd = 0; kd < 64; kd++) {
            float4 kr = *(const float4*)&Kt[kd * PADW + tx * 4];
            float kk[4] = {kr.x, kr.y, kr.z, kr.w};
#pragma unroll
            for (int r = 0; r < 4; r++) {
                float q = Qs[(ty * 4 + r) * PADW + kd];
#pragma unroll
                for (int c = 0; c < 4; c++)
                    s[r][c] = fmaf(q, kk[c], s[r][c]);
            }
        }

        const bool diag = (jt == it);
#pragma unroll
        for (int r = 0; r < 4; r++) {
            int gr = it * 64 + ty * 4 + r;
            bool valid[4];
            float mx = -1e30f;
#pragma unroll
            for (int c = 0; c < 4; c++) {
                int lc = tx * 4 + c;
                int gc = jt * 64 + lc;
                valid[c] = ((!diag) || (gc <= gr)) && (cm[lc] != 0);
                if (valid[c]) mx = fmaxf(mx, s[r][c]);
            }
#pragma unroll
            for (int off = 1; off < 16; off <<= 1)
                mx = fmaxf(mx, __shfl_xor_sync(0xffffffffu, mx, off));

            float mnew = fmaxf(m_i[r], mx);
            float alpha = __expf(m_i[r] - mnew);
            float ls = 0.f;
            float p[4];
#pragma unroll
            for (int c = 0; c < 4; c++) {
                p[c] = valid[c] ? __expf(s[r][c] - mnew) : 0.f;
                ls += p[c];
            }
#pragma unroll
            for (int off = 1; off < 16; off <<= 1)
                ls += __shfl_xor_sync(0xffffffffu, ls, off);

            l_i[r] = l_i[r] * alpha + ls;
            m_i[r] = mnew;
#pragma unroll
            for (int c = 0; c < 4; c++) {
                o[r][c] *= alpha;
                Ps[(ty * 4 + r) * PADW + tx * 4 + c] = p[c];
            }
        }
        __syncthreads();

#pragma unroll 8
        for (int n = 0; n < 64; n++) {
            float4 vr = *(const float4*)&Vs[n * PADW + tx * 4];
            float vv[4] = {vr.x, vr.y, vr.z, vr.w};
#pragma unroll
            for (int r = 0; r < 4; r++) {
                float pp = Ps[(ty * 4 + r) * PADW + n];
#pragma unroll
                for (int c = 0; c < 4; c++)
                    o[r][c] = fmaf(pp, vv[c], o[r][c]);
            }
        }
        __syncthreads();
    }

#pragma unroll
    for (int r = 0; r < 4; r++) {
        int s_idx = it * 64 + ty * 4 + r;
        int rv = mask[b * S_LEN + s_idx];
        float inv = (l_i[r] > 0.f && rv != 0) ? (1.f / l_i[r]) : 0.f;
#pragma unroll
        for (int c = 0; c < 4; c++)
            Oc[((size_t)b * S_LEN + s_idx) * DM + h * HD + tx * 4 + c] = o[r][c] * inv;
    }
}

// ---------------- host ------------------------------------------------------
extern "C" void kernel_launch(void* const* d_in, const int* in_sizes, int n_in,
                              void* d_out, int out_size)
{
    const float* x    = (const float*)d_in[0];
    const int*   mask = (const int*)  d_in[1];
    const float* Wq   = (const float*)d_in[2];
    const float* bq   = (const float*)d_in[3];
    const float* Wk   = (const float*)d_in[4];
    const float* bk   = (const float*)d_in[5];
    const float* Wv   = (const float*)d_in[6];
    const float* bv   = (const float*)d_in[7];
    const float* Wo   = (const float*)d_in[8];
    const float* bo   = (const float*)d_in[9];
    float* out = (float*)d_out;

    float *qp, *kp, *vp, *cp;
    cudaGetSymbolAddress((void**)&qp, g_q);
    cudaGetSymbolAddress((void**)&kp, g_k);
    cudaGetSymbolAddress((void**)&vp, g_v);
    cudaGetSymbolAddress((void**)&cp, g_cat);

    dim3 ggemm(DM / 128, M_TOT / 128);   // (8, 32)
    gemm_tf32<<<ggemm, 256>>>(x, Wq, bq, qp, 1);
    gemm_tf32<<<ggemm, 256>>>(x, Wk, bk, kp, 1);
    gemm_tf32<<<ggemm, 256>>>(x, Wv, bv, vp, 1);

    static int smem_set = 0;
    size_t smem = (size_t)(4 * TILE_F) * sizeof(float) + 64 * sizeof(int);
    if (!smem_set) {
        cudaFuncSetAttribute(attn_kernel, cudaFuncAttributeMaxDynamicSharedMemorySize, (int)smem);
        smem_set = 1;
    }
    dim3 gattn(S_LEN / 64, HEADS, BATCH);  // (32, 16, 2)
    attn_kernel<<<gattn, 256, smem>>>(qp, kp, vp, mask, cp);

    gemm_tf32<<<ggemm, 256>>>(cp, Wo, bo, out, 0);
}

// round 10
// speedup vs baseline: 2.6130x; 1.6277x over previous
#include <cuda_runtime.h>
#include <math.h>

#define BATCH   2
#define S_LEN   2048
#define HEADS   16
#define HD      64
#define DM      1024
#define M_TOT   (BATCH * S_LEN)          // 4096

// ---------------- scratch (device globals: allocation-free) ----------------
__device__ float g_q[BATCH * HEADS * S_LEN * HD];    // [B,H,S,64]
__device__ float g_k[BATCH * HEADS * S_LEN * HD];
__device__ float g_v[BATCH * HEADS * S_LEN * HD];
__device__ float g_cat[BATCH * S_LEN * DM];          // [B,S,H*64]

// ---------------- common tf32 helpers --------------------------------------
__device__ __forceinline__ unsigned f2tf(float x) {
    unsigned r;
    asm("cvt.rna.tf32.f32 %0, %1;" : "=r"(r) : "f"(x));
    return r;
}

__device__ __forceinline__ void mma_tf32(float* c, const unsigned* a, const unsigned* b) {
    asm volatile(
        "mma.sync.aligned.m16n8k8.row.col.f32.tf32.tf32.f32 "
        "{%0,%1,%2,%3}, {%4,%5,%6,%7}, {%8,%9}, {%0,%1,%2,%3};\n"
        : "+f"(c[0]), "+f"(c[1]), "+f"(c[2]), "+f"(c[3])
        : "r"(a[0]), "r"(a[1]), "r"(a[2]), "r"(a[3]), "r"(b[0]), "r"(b[1]));
}

__device__ __forceinline__ float ex2(float x) {
    float r;
    asm("ex2.approx.f32 %0, %1;" : "=f"(r) : "f"(x));
    return r;
}

// ---------------- tf32 tensor-core GEMM ------------------------------------
// C[M,N] = A[M,K] * W[N,K]^T + bias, M=4096, N=1024, K=1024.
#define LDA 36

__global__ __launch_bounds__(256) void gemm_tf32(
    const float* __restrict__ A, const float* __restrict__ W,
    const float* __restrict__ bias, float* __restrict__ C, int scatter)
{
    __shared__ unsigned As[128 * LDA];
    __shared__ unsigned Ws[128 * LDA];

    const int tid  = threadIdx.x;
    const int lane = tid & 31;
    const int wid  = tid >> 5;
    const int wm   = wid >> 2;
    const int wn   = wid & 3;
    const int bm   = blockIdx.y * 128;
    const int bn   = blockIdx.x * 128;

    const int grp = lane >> 2;
    const int tig = lane & 3;

    const int lrow = tid >> 1;
    const int lcol = (tid & 1) * 16;

    const float* Ap = A + (size_t)(bm + lrow) * DM + lcol;
    const float* Wp = W + (size_t)(bn + lrow) * DM + lcol;

    float c[4][4][4];
#pragma unroll
    for (int i = 0; i < 4; i++)
#pragma unroll
        for (int j = 0; j < 4; j++)
#pragma unroll
            for (int r = 0; r < 4; r++) c[i][j][r] = 0.f;

    float4 pa[4], pw[4];
#pragma unroll
    for (int u = 0; u < 4; u++) {
        pa[u] = *(const float4*)(Ap + u * 4);
        pw[u] = *(const float4*)(Wp + u * 4);
    }

    for (int kt = 0; kt < DM; kt += 32) {
        unsigned* as = &As[lrow * LDA + lcol];
        unsigned* ws = &Ws[lrow * LDA + lcol];
#pragma unroll
        for (int u = 0; u < 4; u++) {
            as[u * 4 + 0] = f2tf(pa[u].x);
            as[u * 4 + 1] = f2tf(pa[u].y);
            as[u * 4 + 2] = f2tf(pa[u].z);
            as[u * 4 + 3] = f2tf(pa[u].w);
            ws[u * 4 + 0] = f2tf(pw[u].x);
            ws[u * 4 + 1] = f2tf(pw[u].y);
            ws[u * 4 + 2] = f2tf(pw[u].z);
            ws[u * 4 + 3] = f2tf(pw[u].w);
        }
        __syncthreads();

        if (kt + 32 < DM) {
#pragma unroll
            for (int u = 0; u < 4; u++) {
                pa[u] = *(const float4*)(Ap + kt + 32 + u * 4);
                pw[u] = *(const float4*)(Wp + kt + 32 + u * 4);
            }
        }

#pragma unroll
        for (int ks = 0; ks < 4; ks++) {
            unsigned b[4][2];
#pragma unroll
            for (int j = 0; j < 4; j++) {
                int n = wn * 32 + j * 8 + grp;
                int k = ks * 8 + tig;
                b[j][0] = Ws[n * LDA + k];
                b[j][1] = Ws[n * LDA + k + 4];
            }
#pragma unroll
            for (int i = 0; i < 4; i++) {
                unsigned a[4];
                int m = wm * 64 + i * 16 + grp;
                int k = ks * 8 + tig;
                a[0] = As[m * LDA + k];
                a[1] = As[(m + 8) * LDA + k];
                a[2] = As[m * LDA + k + 4];
                a[3] = As[(m + 8) * LDA + k + 4];
#pragma unroll
                for (int j = 0; j < 4; j++)
                    mma_tf32(c[i][j], a, b[j]);
            }
        }
        __syncthreads();
    }

#pragma unroll
    for (int j = 0; j < 4; j++) {
        int n0 = bn + wn * 32 + j * 8 + 2 * tig;
        float bia0 = bias[n0];
        float bia1 = bias[n0 + 1];
#pragma unroll
        for (int i = 0; i < 4; i++) {
            int m0 = bm + wm * 64 + i * 16 + grp;
            float2 v0 = make_float2(c[i][j][0] + bia0, c[i][j][1] + bia1);
            float2 v1 = make_float2(c[i][j][2] + bia0, c[i][j][3] + bia1);
            if (scatter) {
                int h = n0 >> 6, d = n0 & 63;
                int b0 = m0 >> 11, s0 = m0 & 2047;
                int b1 = (m0 + 8) >> 11, s1 = (m0 + 8) & 2047;
                *(float2*)&C[(((size_t)b0 * HEADS + h) * S_LEN + s0) * HD + d] = v0;
                *(float2*)&C[(((size_t)b1 * HEADS + h) * S_LEN + s1) * HD + d] = v1;
            } else {
                *(float2*)&C[(size_t)m0 * DM + n0] = v0;
                *(float2*)&C[(size_t)(m0 + 8) * DM + n0] = v1;
            }
        }
    }
}

// ---------------- tensor-core flash attention (tf32) ------------------------
// grid (S/64, H, B), 128 threads = 4 warps; warp w owns q-rows [16w,16w+16).
// smem layout (4B words):
//   Qs [64*68]  tf32 Q (pre-scaled by 0.125*log2e)
//   Ks [64*68]  tf32 K (kv-major)
//   Vt [64*68]  tf32 V^T (d-major)
//   Ps [4*16*68] per-warp P staging (aliases Vn = fp32 V scratch [64*65])
//   cm [64]
#define QS_OFF 0
#define KS_OFF 4352
#define VT_OFF 8704
#define PS_OFF 13056
#define CM_OFF 17408
#define SMEM_WORDS 17472

__global__ __launch_bounds__(128) void attn_tc(
    const float* __restrict__ Qb, const float* __restrict__ Kb,
    const float* __restrict__ Vb, const int* __restrict__ mask,
    float* __restrict__ Oc)
{
    extern __shared__ unsigned sm[];
    unsigned* Qs = sm + QS_OFF;
    unsigned* Ks = sm + KS_OFF;
    unsigned* Vt = sm + VT_OFF;
    unsigned* Ps = sm + PS_OFF;
    float*    Vn = (float*)(sm + PS_OFF);
    int*      cm = (int*)(sm + CM_OFF);

    const int it  = blockIdx.x;
    const int h   = blockIdx.y;
    const int b   = blockIdx.z;
    const int tid = threadIdx.x;
    const int w    = tid >> 5;
    const int lane = tid & 31;
    const int grp  = lane >> 2;
    const int tig  = lane & 3;

    const size_t bh = ((size_t)b * HEADS + h) * S_LEN * HD;
    const float qscale = 0.125f * 1.4426950408889634f;   // 1/sqrt(64) * log2(e)

    // ---- load Q tile (scaled, tf32) ----
    for (int e = tid; e < 1024; e += 128) {
        int r = e >> 4, c = (e & 15) << 2;
        float4 v = *(const float4*)(Qb + bh + (size_t)(it * 64 + r) * HD + c);
        unsigned* q = &Qs[r * 68 + c];
        q[0] = f2tf(v.x * qscale);
        q[1] = f2tf(v.y * qscale);
        q[2] = f2tf(v.z * qscale);
        q[3] = f2tf(v.w * qscale);
    }

    const int qr0 = 16 * w + grp;           // local q-row (second row = qr0+8)
    const int qbase0 = qr0 * 68;
    const int qbase1 = qbase0 + 8 * 68;
    unsigned* Pw = Ps + w * 1088;

    float m0 = -1e30f, m1 = -1e30f, l0 = 0.f, l1 = 0.f;
    float o[8][4];
#pragma unroll
    for (int nt = 0; nt < 8; nt++)
#pragma unroll
        for (int r = 0; r < 4; r++) o[nt][r] = 0.f;

    for (int jt = 0; jt <= it; jt++) {
        __syncthreads();   // prior iter's readers of Ks/Vt/Ps done

        // ---- K -> Ks (tf32), V -> Vn (fp32 scratch, stride 65) ----
        for (int e = tid; e < 1024; e += 128) {
            int r = e >> 4, c = (e & 15) << 2;
            float4 kv = *(const float4*)(Kb + bh + (size_t)(jt * 64 + r) * HD + c);
            unsigned* ks = &Ks[r * 68 + c];
            ks[0] = f2tf(kv.x); ks[1] = f2tf(kv.y);
            ks[2] = f2tf(kv.z); ks[3] = f2tf(kv.w);
            float4 vv = *(const float4*)(Vb + bh + (size_t)(jt * 64 + r) * HD + c);
            float* vn = &Vn[r * 65 + c];
            vn[0] = vv.x; vn[1] = vv.y; vn[2] = vv.z; vn[3] = vv.w;
        }
        if (tid < 64) cm[tid] = mask[b * S_LEN + jt * 64 + tid];
        __syncthreads();   // Ks/Vn/cm ready

        // ---- S = Q K^T (m16 x n64 per warp) ----
        float s[8][4];
#pragma unroll
        for (int nt = 0; nt < 8; nt++)
#pragma unroll
            for (int r = 0; r < 4; r++) s[nt][r] = 0.f;

#pragma unroll
        for (int kk = 0; kk < 8; kk++) {
            unsigned a[4];
            a[0] = Qs[qbase0 + kk * 8 + tig];
            a[1] = Qs[qbase1 + kk * 8 + tig];
            a[2] = Qs[qbase0 + kk * 8 + tig + 4];
            a[3] = Qs[qbase1 + kk * 8 + tig + 4];
#pragma unroll
            for (int nt = 0; nt < 8; nt++) {
                unsigned bb[2];
                bb[0] = Ks[(nt * 8 + grp) * 68 + kk * 8 + tig];
                bb[1] = Ks[(nt * 8 + grp) * 68 + kk * 8 + tig + 4];
                mma_tf32(s[nt], a, bb);
            }
        }

        // ---- build Vt (d-major, tf32) from Vn; conflict-free both sides ----
        {
            int rkv  = ((w & 1) << 5) | lane;
            int dbas = (w >> 1) << 5;
#pragma unroll 8
            for (int i = 0; i < 32; i++) {
                int d = dbas + i;
                Vt[d * 68 + rkv] = f2tf(Vn[rkv * 65 + d]);
            }
        }

        // ---- mask + online softmax (registers) ----
        const bool diag = (jt == it);
        float mx0 = -1e30f, mx1 = -1e30f;
#pragma unroll
        for (int nt = 0; nt < 8; nt++) {
            int lc0 = nt * 8 + 2 * tig;
            int lc1 = lc0 + 1;
            bool c0 = cm[lc0] != 0;
            bool c1 = cm[lc1] != 0;
            bool v00 = c0 && (!diag || lc0 <= qr0);
            bool v01 = c1 && (!diag || lc1 <= qr0);
            bool v10 = c0 && (!diag || lc0 <= qr0 + 8);
            bool v11 = c1 && (!diag || lc1 <= qr0 + 8);
            s[nt][0] = v00 ? s[nt][0] : -1e30f;
            s[nt][1] = v01 ? s[nt][1] : -1e30f;
            s[nt][2] = v10 ? s[nt][2] : -1e30f;
            s[nt][3] = v11 ? s[nt][3] : -1e30f;
            mx0 = fmaxf(mx0, fmaxf(s[nt][0], s[nt][1]));
            mx1 = fmaxf(mx1, fmaxf(s[nt][2], s[nt][3]));
        }
        mx0 = fmaxf(mx0, __shfl_xor_sync(0xffffffffu, mx0, 1));
        mx0 = fmaxf(mx0, __shfl_xor_sync(0xffffffffu, mx0, 2));
        mx1 = fmaxf(mx1, __shfl_xor_sync(0xffffffffu, mx1, 1));
        mx1 = fmaxf(mx1, __shfl_xor_sync(0xffffffffu, mx1, 2));

        float mn0 = fmaxf(m0, mx0);
        float mn1 = fmaxf(m1, mx1);
        float al0 = ex2(m0 - mn0);
        float al1 = ex2(m1 - mn1);
        float ls0 = 0.f, ls1 = 0.f;
#pragma unroll
        for (int nt = 0; nt < 8; nt++) {
            s[nt][0] = ex2(s[nt][0] - mn0); ls0 += s[nt][0];
            s[nt][1] = ex2(s[nt][1] - mn0); ls0 += s[nt][1];
            s[nt][2] = ex2(s[nt][2] - mn1); ls1 += s[nt][2];
            s[nt][3] = ex2(s[nt][3] - mn1); ls1 += s[nt][3];
        }
        ls0 += __shfl_xor_sync(0xffffffffu, ls0, 1);
        ls0 += __shfl_xor_sync(0xffffffffu, ls0, 2);
        ls1 += __shfl_xor_sync(0xffffffffu, ls1, 1);
        ls1 += __shfl_xor_sync(0xffffffffu, ls1, 2);

        l0 = l0 * al0 + ls0;
        l1 = l1 * al1 + ls1;
        m0 = mn0;
        m1 = mn1;
#pragma unroll
        for (int nt = 0; nt < 8; nt++) {
            o[nt][0] *= al0; o[nt][1] *= al0;
            o[nt][2] *= al1; o[nt][3] *= al1;
        }

        __syncthreads();   // Vt complete everywhere; Vn readers done (Ps may now alias-write)

        // ---- stage P (tf32) in per-warp smem, reshape C-frag -> A-frag ----
#pragma unroll
        for (int nt = 0; nt < 8; nt++) {
            int cbase = nt * 8 + 2 * tig;
            Pw[grp * 68 + cbase]           = f2tf(s[nt][0]);
            Pw[grp * 68 + cbase + 1]       = f2tf(s[nt][1]);
            Pw[(grp + 8) * 68 + cbase]     = f2tf(s[nt][2]);
            Pw[(grp + 8) * 68 + cbase + 1] = f2tf(s[nt][3]);
        }
        __syncwarp();

        // ---- O += P V ----
#pragma unroll
        for (int kk = 0; kk < 8; kk++) {
            unsigned a[4];
            a[0] = Pw[grp * 68 + kk * 8 + tig];
            a[1] = Pw[(grp + 8) * 68 + kk * 8 + tig];
            a[2] = Pw[grp * 68 + kk * 8 + tig + 4];
            a[3] = Pw[(grp + 8) * 68 + kk * 8 + tig + 4];
#pragma unroll
            for (int nt = 0; nt < 8; nt++) {
                unsigned bb[2];
                bb[0] = Vt[(nt * 8 + grp) * 68 + kk * 8 + tig];
                bb[1] = Vt[(nt * 8 + grp) * 68 + kk * 8 + tig + 4];
                mma_tf32(o[nt], a, bb);
            }
        }
    }

    // ---- epilogue: normalize, write concat [B,S,H*64] ----
    int g0 = it * 64 + qr0;
    int g1 = g0 + 8;
    int rv0 = mask[b * S_LEN + g0];
    int rv1 = mask[b * S_LEN + g1];
    float inv0 = (rv0 != 0 && m0 > -1e29f) ? (1.f / l0) : 0.f;
    float inv1 = (rv1 != 0 && m1 > -1e29f) ? (1.f / l1) : 0.f;
    size_t ro0 = ((size_t)b * S_LEN + g0) * DM + h * 64;
    size_t ro1 = ((size_t)b * S_LEN + g1) * DM + h * 64;
#pragma unroll
    for (int nt = 0; nt < 8; nt++) {
        int cc = nt * 8 + 2 * tig;
        float2 w0 = make_float2(o[nt][0] * inv0, o[nt][1] * inv0);
        float2 w1 = make_float2(o[nt][2] * inv1, o[nt][3] * inv1);
        *(float2*)&Oc[ro0 + cc] = w0;
        *(float2*)&Oc[ro1 + cc] = w1;
    }
}

// ---------------- host ------------------------------------------------------
extern "C" void kernel_launch(void* const* d_in, const int* in_sizes, int n_in,
                              void* d_out, int out_size)
{
    const float* x    = (const float*)d_in[0];
    const int*   mask = (const int*)  d_in[1];
    const float* Wq   = (const float*)d_in[2];
    const float* bq   = (const float*)d_in[3];
    const float* Wk   = (const float*)d_in[4];
    const float* bk   = (const float*)d_in[5];
    const float* Wv   = (const float*)d_in[6];
    const float* bv   = (const float*)d_in[7];
    const float* Wo   = (const float*)d_in[8];
    const float* bo   = (const float*)d_in[9];
    float* out = (float*)d_out;

    float *qp, *kp, *vp, *cp;
    cudaGetSymbolAddress((void**)&qp, g_q);
    cudaGetSymbolAddress((void**)&kp, g_k);
    cudaGetSymbolAddress((void**)&vp, g_v);
    cudaGetSymbolAddress((void**)&cp, g_cat);

    dim3 ggemm(DM / 128, M_TOT / 128);   // (8, 32)
    gemm_tf32<<<ggemm, 256>>>(x, Wq, bq, qp, 1);
    gemm_tf32<<<ggemm, 256>>>(x, Wk, bk, kp, 1);
    gemm_tf32<<<ggemm, 256>>>(x, Wv, bv, vp, 1);

    static int smem_set = 0;
    size_t smem = (size_t)SMEM_WORDS * 4;   // 69888 B
    if (!smem_set) {
        cudaFuncSetAttribute(attn_tc, cudaFuncAttributeMaxDynamicSharedMemorySize, (int)smem);
        smem_set = 1;
    }
    dim3 gattn(S_LEN / 64, HEADS, BATCH);  // (32, 16, 2)
    attn_tc<<<gattn, 128, smem>>>(qp, kp, vp, mask, cp);

    gemm_tf32<<<ggemm, 256>>>(cp, Wo, bo, out, 0);
}